// round 4
// baseline (speedup 1.0000x reference)
#include <cuda_runtime.h>
#include <cstdint>

#define IMG  224
#define HW   (IMG * IMG)        // 50176
#define BX   32                 // output tile x (outer dim of flat i)
#define BY   32                 // output tile y (inner dim of flat i)
#define XW   48                 // staged row width in floats (192 B, 16B-mult)
#define YH   43                 // staged rows (y-halo 5/6)
#define PLANE (XW * YH)         // 2064 floats per channel plane
#define ROWB (XW * 4)           // 192 bytes per row copy
#define NJOBS (6 * YH)          // 258 bulk row copies per block
#define TXBYTES (NJOBS * ROWB)  // 49536
#define NT   1024

// dynamic smem layout (bytes):
//   [0,            49536)  6 gather planes (im1 ch0..2, im2 ch0..2), row stride 192B
//   [49536,        49552)  mbarrier (8B used, 16B slot)
//   [49552,        66448)  io remap: 4 planes of [32][33] floats (aliased as
//                          3 output planes of [32][33] after the C/M reads)
#define SMEM_BYTES 66448
#define IOPITCH (32 * 33)       // 1056 floats per remap plane

__device__ __forceinline__ uint32_t s2u(const void* p) {
    uint32_t a;
    asm("{ .reg .u64 t; cvta.to.shared.u64 t, %1; cvt.u32.u64 %0, t; }"
        : "=r"(a) : "l"(p));
    return a;
}

__device__ __forceinline__ void mbar_init(uint32_t mbar, uint32_t cnt) {
    asm volatile("mbarrier.init.shared.b64 [%0], %1;" :: "r"(mbar), "r"(cnt) : "memory");
}
__device__ __forceinline__ void mbar_expect_tx(uint32_t mbar, uint32_t bytes) {
    asm volatile("mbarrier.arrive.expect_tx.shared.b64 _, [%0], %1;"
                 :: "r"(mbar), "r"(bytes) : "memory");
}
__device__ __forceinline__ void mbar_wait0(uint32_t mbar) {
    uint32_t done;
    asm volatile(
        "{\n\t.reg .pred p;\n\t"
        "mbarrier.try_wait.parity.acquire.cta.shared::cta.b64 p, [%1], 0;\n\t"
        "selp.b32 %0, 1, 0, p;\n\t}"
        : "=r"(done) : "r"(mbar) : "memory");
    if (!done) {
        asm volatile(
            "{\n\t.reg .pred P1;\n\t"
            "WL_%=:\n\t"
            "mbarrier.try_wait.parity.acquire.cta.shared::cta.b64 P1, [%0], 0, 0x989680;\n\t"
            "@P1 bra.uni WD_%=;\n\t"
            "bra.uni WL_%=;\n\t"
            "WD_%=:\n\t}"
            :: "r"(mbar) : "memory");
    }
}
__device__ __forceinline__ void bulk_cp_row(uint32_t dst, const void* src, uint32_t mbar) {
    asm volatile(
        "cp.async.bulk.shared::cta.global.mbarrier::complete_tx::bytes [%0], [%1], %2, [%3];"
        :: "r"(dst), "l"(src), "n"(ROWB), "r"(mbar) : "memory");
}

__global__ __launch_bounds__(NT) void vm_kernel(
    const float* __restrict__ im1, const float* __restrict__ im2,
    const float* __restrict__ C,   const float* __restrict__ M1,
    const float* __restrict__ M2,  float* __restrict__ out)
{
    extern __shared__ __align__(16) float smem[];
    float*    planes = smem;                          // 6*PLANE floats
    uint64_t* mbarp  = (uint64_t*)(smem + 6 * PLANE); // 16B slot
    float*    io     = smem + 6 * PLANE + 4;          // 4 (then 3) x IOPITCH

    const int tid = threadIdx.x;
    const int X0 = blockIdx.x * BX;
    const int Y0 = blockIdx.y * BY;
    const int n  = blockIdx.z;

    // staged window, clamped fully inside the image (sx0 multiple of 4 ->
    // 16B-aligned global rows; no OOB, no fill)
    const int sx0 = min(max(X0 - 8, 0), IMG - XW);
    const int sy0 = min(max(Y0 - 5, 0), IMG - YH);

    const float* b1 = im1 + n * 3 * HW;
    const float* b2 = im2 + n * 3 * HW;

    const uint32_t splanes = s2u(planes);
    const uint32_t mbar    = s2u(mbarp);

    if (tid == 0) { mbar_init(mbar, 1); mbar_expect_tx(mbar, TXBYTES); }
    __syncthreads();

    // ── TMA bulk staging: 258 row copies, no LSU traffic ──
    if (tid < NJOBS) {
        int p = tid / YH;            // plane 0..5
        int r = tid - p * YH;        // row 0..42
        const float* srcplane = (p < 3) ? (b1 + p * HW) : (b2 + (p - 3) * HW);
        const float* src = srcplane + (sy0 + r) * IMG + sx0;
        uint32_t dst = splanes + (uint32_t)(p * PLANE + r * XW) * 4u;
        bulk_cp_row(dst, src, mbar);
    }

    // ── C/M loads with coalesced (lanes-along-y) mapping; remap via smem ──
    const int xp = tid >> 5;         // 0..31
    const int yp = tid & 31;
    const int i_io = (X0 + xp) * IMG + (Y0 + yp);
    {
        float c1 = __ldg(C  + (n * 2) * HW + i_io);
        float c2 = __ldg(C  + (n * 2 + 1) * HW + i_io);
        float a1 = __ldg(M1 + n * HW + i_io);
        float a2 = __ldg(M2 + n * HW + i_io);
        int t = xp * 33 + yp;
        io[0 * IOPITCH + t] = c1;
        io[1 * IOPITCH + t] = c2;
        io[2 * IOPITCH + t] = a1;
        io[3 * IOPITCH + t] = a2;
    }
    __syncthreads();

    // ── compute mapping: lanes along x (conflict-free gather banks) ──
    const int l = tid & 31;          // x within tile
    const int w = tid >> 5;          // y within tile
    float Cx, Cy, m1v, m2v;
    {
        int t = l * 33 + w;          // bank = l*33+w mod 32 = l+w -> conflict-free
        Cx  = io[0 * IOPITCH + t];
        Cy  = io[1 * IOPITCH + t];
        m1v = io[2 * IOPITCH + t];
        m2v = io[3 * IOPITCH + t];
    }
    __syncthreads();                 // io region now free for output reuse

    mbar_wait0(mbar);                // staged planes ready

    const float fxv = (float)(X0 + l);
    const float fyv = (float)(Y0 + w);
    const float lox = (float)sx0, hix = (float)(sx0 + XW - 1);
    const float loy = (float)sy0, hiy = (float)(sy0 + YH - 1);

    float res[3];
#pragma unroll
    for (int s = 0; s < 2; s++) {
        const float px = s ? (fxv - Cx) : (fxv + Cx);
        const float py = s ? (fyv - Cy) : (fyv + Cy);
        const float* gim = s ? b2 : b1;
        const float* pl  = planes + (s ? 3 * PLANE : 0);

        float fx = floorf(px), cx = ceilf(px);
        float fy = floorf(py), cy = ceilf(py);
        float wfx = 1.0f - (px - fx);
        float wcx = 1.0f - (cx - px);
        float wfy = 1.0f - (py - fy);
        float wcy = 1.0f - (cy - py);
        float wff = wfx * wfy, wcf = wcx * wfy;
        float wfc = wfx * wcy, wcc = wcx * wcy;

        float v0, v1, v2;
        if (fx >= lox && cx <= hix && fy >= loy && cy <= hiy) {
            // window is inside the image, so taps are in-image: flat-index
            // truncate/clip in the reference is a no-op here.
            int c0 = (int)fx - sx0;
            int dc = (int)cx - sx0 - c0;     // 0 or 1
            int r0 = (int)fy - sy0;
            int r1 = (int)cy - sy0;
            int t00 = r0 * XW + c0;
            int t10 = r1 * XW + c0;
            int t01 = t00 + dc;
            int t11 = t10 + dc;
#pragma unroll
            for (int ch = 0; ch < 3; ch++) {
                const float* p = pl + ch * PLANE;
                float v = wff * p[t00];
                v = fmaf(wcf, p[t01], v);
                v = fmaf(wfc, p[t10], v);
                v = fmaf(wcc, p[t11], v);
                if (ch == 0) v0 = v; else if (ch == 1) v1 = v; else v2 = v;
            }
        } else {
            // exact reference fallback: ind = clip(int32(nx + 224*ny), 0, HW-1)
            int iff = (int)(fx + 224.0f * fy);
            int icf = (int)(cx + 224.0f * fy);
            int ifc = (int)(fx + 224.0f * cy);
            int icc = (int)(cx + 224.0f * cy);
            iff = min(max(iff, 0), HW - 1);
            icf = min(max(icf, 0), HW - 1);
            ifc = min(max(ifc, 0), HW - 1);
            icc = min(max(icc, 0), HW - 1);
            float acc[3];
#pragma unroll
            for (int ch = 0; ch < 3; ch++) {
                const float* p = gim + ch * HW;
                float v = wff * __ldg(p + iff);
                v = fmaf(wcf, __ldg(p + icf), v);
                v = fmaf(wfc, __ldg(p + ifc), v);
                v = fmaf(wcc, __ldg(p + icc), v);
                acc[ch] = v;
            }
            v0 = acc[0]; v1 = acc[1]; v2 = acc[2];
        }
        if (s == 0) { res[0] = v0 * m1v; res[1] = v1 * m1v; res[2] = v2 * m1v; }
        else        { res[0] = fmaf(v0, m2v, res[0]);
                      res[1] = fmaf(v1, m2v, res[1]);
                      res[2] = fmaf(v2, m2v, res[2]); }
    }

    // ── output remap: store (l,w)-indexed, write coalesced (xp,yp)-indexed ──
    {
        int t = l * 33 + w;
#pragma unroll
        for (int ch = 0; ch < 3; ch++)
            io[ch * IOPITCH + t] = res[ch];
    }
    __syncthreads();
    {
        float* outn = out + n * 3 * HW;
        int t = xp * 33 + yp;
#pragma unroll
        for (int ch = 0; ch < 3; ch++)
            outn[ch * HW + i_io] = io[ch * IOPITCH + t];
    }
}

extern "C" void kernel_launch(void* const* d_in, const int* in_sizes, int n_in,
                              void* d_out, int out_size)
{
    const float* im1 = (const float*)d_in[0];
    const float* im2 = (const float*)d_in[1];
    const float* C   = (const float*)d_in[2];
    const float* M1  = (const float*)d_in[3];
    const float* M2  = (const float*)d_in[4];
    float* out = (float*)d_out;

    cudaFuncSetAttribute(vm_kernel, cudaFuncAttributeMaxDynamicSharedMemorySize,
                         SMEM_BYTES);

    dim3 block(NT, 1, 1);
    dim3 grid(IMG / BX, IMG / BY, 64);   // 7 x 7 x 64 = 3136 blocks
    vm_kernel<<<grid, block, SMEM_BYTES>>>(im1, im2, C, M1, M2, out);
}

// round 5
// speedup vs baseline: 1.5101x; 1.5101x over previous
#include <cuda_runtime.h>
#include <cstdint>

#define IMG  224
#define HW   (IMG * IMG)        // 50176
#define BXT  32                 // tile x extent (outer dim of flat i)
#define BYT  16                 // tile y extent (inner dim of flat i)
#define XW   44                 // staged row width (floats, 16B-multiple)
#define YH   27                 // staged rows (y halo 5/6)
#define PLANE (XW * YH)         // 1188 floats
#define NT   512
#define NJOBS (6 * YH * (XW / 4))  // 1782 16B cp.async copies
#define IOP  (32 * 17)          // 544 floats per io remap plane

__device__ __forceinline__ uint32_t s2u(const void* p) {
    uint32_t a;
    asm("{ .reg .u64 t; cvta.to.shared.u64 t, %1; cvt.u32.u64 %0, t; }"
        : "=r"(a) : "l"(p));
    return a;
}

__global__ __launch_bounds__(NT, 3) void vm_kernel(
    const float* __restrict__ im1, const float* __restrict__ im2,
    const float* __restrict__ C,   const float* __restrict__ M1,
    const float* __restrict__ M2,  float* __restrict__ out)
{
    // static smem: 6 gather planes + io remap region
    __shared__ __align__(16) float planes[6 * PLANE];   // 28512 B
    __shared__ __align__(16) float io[4 * IOP];         // 8704 B (reused for out)

    const int tid = threadIdx.x;
    const int X0 = blockIdx.x * BXT;
    const int Y0 = blockIdx.y * BYT;
    const int n  = blockIdx.z;

    // staged window fully inside image; sx0 multiple of 4 -> 16B-aligned rows
    const int sx0 = min(max(X0 - 8, 0), IMG - XW);   // x halo 8 left / 4 right
    const int sy0 = min(max(Y0 - 5, 0), IMG - YH);   // y halo 5 / 6

    const float* b1 = im1 + n * 3 * HW;
    const float* b2 = im2 + n * 3 * HW;

    const uint32_t sbase = s2u(planes);

    // ── async staging: 1782 x 16B cp.async (LDGSTS), overlapped with I/O ──
    {
        int j = tid;
#pragma unroll
        for (int it = 0; it < 4; it++, j += NT) {
            if (j < NJOBS) {
                int rowid = j / 11;            // 0..161  (11 float4 per row)
                int c4    = j - rowid * 11;
                int p     = rowid / YH;        // plane 0..5
                int r     = rowid - p * YH;    // row 0..26
                const float* srcp = (p < 3) ? (b1 + p * HW) : (b2 + (p - 3) * HW);
                const float* src  = srcp + (sy0 + r) * IMG + sx0 + c4 * 4;
                uint32_t dst = sbase + (uint32_t)((p * YH + r) * XW + c4 * 4) * 4u;
                asm volatile("cp.async.cg.shared.global [%0], [%1], 16;"
                             :: "r"(dst), "l"(src));
            }
        }
        asm volatile("cp.async.commit_group;");
    }

    // ── C/M loads with coalesced (y-inner) mapping, remapped through smem ──
    const int xp = tid >> 4;           // 0..31
    const int yp = tid & 15;           // 0..15
    const int i_io = (X0 + xp) * IMG + (Y0 + yp);
    {
        float c1 = __ldg(C  + (n * 2) * HW + i_io);
        float c2 = __ldg(C  + (n * 2 + 1) * HW + i_io);
        float a1 = __ldg(M1 + n * HW + i_io);
        float a2 = __ldg(M2 + n * HW + i_io);
        int t = xp * 17 + yp;
        io[0 * IOP + t] = c1;
        io[1 * IOP + t] = c2;
        io[2 * IOP + t] = a1;
        io[3 * IOP + t] = a2;
    }
    __syncthreads();

    // compute mapping: lanes along x (conflict-free gather banks)
    const int l = tid & 31;            // x offset in tile
    const int w = tid >> 5;            // y offset in tile
    float Cx, Cy, m1v, m2v;
    {
        int t = l * 17 + w;            // bank 17l + w mod 32 -> conflict-free
        Cx  = io[0 * IOP + t];
        Cy  = io[1 * IOP + t];
        m1v = io[2 * IOP + t];
        m2v = io[3 * IOP + t];
    }

    // wait for staged planes (also fences io reuse below)
    asm volatile("cp.async.wait_group 0;");
    __syncthreads();

    const float fxv = (float)(X0 + l);
    const float fyv = (float)(Y0 + w);
    const float lox = (float)sx0, hix = (float)(sx0 + XW - 1);
    const float loy = (float)sy0, hiy = (float)(sy0 + YH - 1);

    float res[3];
#pragma unroll
    for (int s = 0; s < 2; s++) {
        const float px = s ? (fxv - Cx) : (fxv + Cx);
        const float py = s ? (fyv - Cy) : (fyv + Cy);
        const float* gim = s ? b2 : b1;
        const float* pl  = planes + (s ? 3 * PLANE : 0);

        float fx = floorf(px), cx = ceilf(px);
        float fy = floorf(py), cy = ceilf(py);
        float wfx = 1.0f - (px - fx);
        float wcx = 1.0f - (cx - px);
        float wfy = 1.0f - (py - fy);
        float wcy = 1.0f - (cy - py);
        float wff = wfx * wfy, wcf = wcx * wfy;
        float wfc = wfx * wcy, wcc = wcx * wcy;

        float v0, v1, v2;
        if (fx >= lox && cx <= hix && fy >= loy && cy <= hiy) {
            // in-window taps are in-image: reference's flat-index clip is a
            // no-op and smem holds the exact values.
            int c0 = (int)fx - sx0;
            int dc = (int)cx - sx0 - c0;     // 0 or 1 (0 in degenerate case)
            int r0 = (int)fy - sy0;
            int r1 = (int)cy - sy0;
            int t00 = r0 * XW + c0;
            int t10 = r1 * XW + c0;
            int t01 = t00 + dc;
            int t11 = t10 + dc;
            float acc[3];
#pragma unroll
            for (int ch = 0; ch < 3; ch++) {
                const float* p = pl + ch * PLANE;
                float v = wff * p[t00];
                v = fmaf(wcf, p[t01], v);
                v = fmaf(wfc, p[t10], v);
                v = fmaf(wcc, p[t11], v);
                acc[ch] = v;
            }
            v0 = acc[0]; v1 = acc[1]; v2 = acc[2];
        } else {
            // exact reference fallback: ind = clip(int32(nx + 224*ny), 0, HW-1)
            int iff = (int)(fx + 224.0f * fy);
            int icf = (int)(cx + 224.0f * fy);
            int ifc = (int)(fx + 224.0f * cy);
            int icc = (int)(cx + 224.0f * cy);
            iff = min(max(iff, 0), HW - 1);
            icf = min(max(icf, 0), HW - 1);
            ifc = min(max(ifc, 0), HW - 1);
            icc = min(max(icc, 0), HW - 1);
            float acc[3];
#pragma unroll
            for (int ch = 0; ch < 3; ch++) {
                const float* p = gim + ch * HW;
                float v = wff * __ldg(p + iff);
                v = fmaf(wcf, __ldg(p + icf), v);
                v = fmaf(wfc, __ldg(p + ifc), v);
                v = fmaf(wcc, __ldg(p + icc), v);
                acc[ch] = v;
            }
            v0 = acc[0]; v1 = acc[1]; v2 = acc[2];
        }
        if (s == 0) { res[0] = v0 * m1v; res[1] = v1 * m1v; res[2] = v2 * m1v; }
        else        { res[0] = fmaf(v0, m2v, res[0]);
                      res[1] = fmaf(v1, m2v, res[1]);
                      res[2] = fmaf(v2, m2v, res[2]); }
    }

    // ── output remap: store compute-mapped, write coalesced y-inner mapped ──
    {
        int t = l * 17 + w;
#pragma unroll
        for (int ch = 0; ch < 3; ch++)
            io[ch * IOP + t] = res[ch];
    }
    __syncthreads();
    {
        float* outn = out + n * 3 * HW;
        int t = xp * 17 + yp;
#pragma unroll
        for (int ch = 0; ch < 3; ch++)
            outn[ch * HW + i_io] = io[ch * IOP + t];
    }
}

extern "C" void kernel_launch(void* const* d_in, const int* in_sizes, int n_in,
                              void* d_out, int out_size)
{
    const float* im1 = (const float*)d_in[0];
    const float* im2 = (const float*)d_in[1];
    const float* C   = (const float*)d_in[2];
    const float* M1  = (const float*)d_in[3];
    const float* M2  = (const float*)d_in[4];
    float* out = (float*)d_out;

    dim3 block(NT, 1, 1);
    dim3 grid(IMG / BXT, IMG / BYT, 64);   // 7 x 14 x 64 = 6272 blocks
    vm_kernel<<<grid, block>>>(im1, im2, C, M1, M2, out);
}

// round 6
// speedup vs baseline: 1.5816x; 1.0474x over previous
#include <cuda_runtime.h>
#include <cstdint>

#define IMG  224
#define HW   (IMG * IMG)        // 50176
#define BXT  16                 // tile x extent (outer dim of flat i)
#define BYT  32                 // tile y extent (inner dim of flat i, lanes)
#define XWU  27                 // used window width in x (16 + 5 + 5 + 1)
#define SW   29                 // smem row stride (ODD -> conflict-free banks)
#define YH   43                 // window rows in y (32 + 5 + 5 + 1)
#define PLANE (SW * YH)         // 1247 floats
#define NT   512

__device__ __forceinline__ uint32_t s2u(const void* p) {
    uint32_t a;
    asm("{ .reg .u64 t; cvta.to.shared.u64 t, %1; cvt.u32.u64 %0, t; }"
        : "=r"(a) : "l"(p));
    return a;
}

__global__ __launch_bounds__(NT, 4) void vm_kernel(
    const float* __restrict__ im1, const float* __restrict__ im2,
    const float* __restrict__ C,   const float* __restrict__ M1,
    const float* __restrict__ M2,  float* __restrict__ out)
{
    __shared__ float planes[6 * PLANE];   // 29928 B

    const int tid = threadIdx.x;
    const int l   = tid & 31;             // lane: y within tile
    const int w   = tid >> 5;             // warp: x within tile
    const int X0 = blockIdx.x * BXT;
    const int Y0 = blockIdx.y * BYT;
    const int n  = blockIdx.z;

    // staged window fully inside the image (fallback handles the tails exactly)
    const int sx0 = min(max(X0 - 5, 0), IMG - XWU);
    const int sy0 = min(max(Y0 - 5, 0), IMG - YH);

    const float* b1 = im1 + n * 3 * HW;
    const float* b2 = im2 + n * 3 * HW;

    const uint32_t sbase = s2u(planes);

    // ── async staging: 4B cp.async, odd smem stride, division-free mapping.
    //    warp w covers rows {w, w+16, w+32} of each of the 6 planes; lanes
    //    0..26 carry one float each (consecutive -> coalesced global reads).
    {
        const bool lok = (l < XWU);
#pragma unroll
        for (int p = 0; p < 6; p++) {
            const float* sp = (p < 3) ? (b1 + p * HW) : (b2 + (p - 3) * HW);
#pragma unroll
            for (int rr = 0; rr < 3; rr++) {
                int r = w + rr * 16;
                if (lok && r < YH) {
                    const float* src = sp + (sy0 + r) * IMG + sx0 + l;
                    uint32_t dst = sbase + (uint32_t)((p * YH + r) * SW + l) * 4u;
                    asm volatile("cp.async.ca.shared.global [%0], [%1], 4;"
                                 :: "r"(dst), "l"(src));
                }
            }
        }
        asm volatile("cp.async.commit_group;");
    }

    // ── coalesced direct I/O (lanes along y) — overlapped with staging ──
    const int x = X0 + w;
    const int y = Y0 + l;
    const int i = x * IMG + y;

    float Cx  = __ldg(C  + (n * 2) * HW + i);
    float Cy  = __ldg(C  + (n * 2 + 1) * HW + i);
    float m1v = __ldg(M1 + n * HW + i);
    float m2v = __ldg(M2 + n * HW + i);

    // hoist all tap-independent math above the wait
    const float fxv = (float)x, fyv = (float)y;
    const float lox = (float)sx0, hix = (float)(sx0 + XWU - 1);
    const float loy = (float)sy0, hiy = (float)(sy0 + YH - 1);

    float pxs[2], pys[2];
    pxs[0] = fxv + Cx; pys[0] = fyv + Cy;
    pxs[1] = fxv - Cx; pys[1] = fyv - Cy;

    asm volatile("cp.async.wait_group 0;");
    __syncthreads();

    float res[3];
#pragma unroll
    for (int s = 0; s < 2; s++) {
        const float px = pxs[s], py = pys[s];
        const float* gim = s ? b2 : b1;
        const float* pl  = planes + (s ? 3 * PLANE : 0);

        float fx = floorf(px), cx = ceilf(px);
        float fy = floorf(py), cy = ceilf(py);
        float wfx = 1.0f - (px - fx);
        float wcx = 1.0f - (cx - px);
        float wfy = 1.0f - (py - fy);
        float wcy = 1.0f - (cy - py);
        float wff = wfx * wfy, wcf = wcx * wfy;
        float wfc = wfx * wcy, wcc = wcx * wcy;

        float v0, v1, v2;
        if (fx >= lox && cx <= hix && fy >= loy && cy <= hiy) {
            // window ⊂ image, so taps are in-image: the reference's flat-index
            // truncate/clip is a no-op and smem holds the exact values.
            int c0 = (int)fx - sx0;
            int dc = (int)cx - sx0 - c0;     // 0 or 1 (0 in degenerate case)
            int r0 = (int)fy - sy0;
            int r1 = (int)cy - sy0;
            int t00 = r0 * SW + c0;          // bank ~ 29*lane -> conflict-free
            int t10 = r1 * SW + c0;
            int t01 = t00 + dc;
            int t11 = t10 + dc;
            float acc[3];
#pragma unroll
            for (int ch = 0; ch < 3; ch++) {
                const float* p = pl + ch * PLANE;
                float v = wff * p[t00];
                v = fmaf(wcf, p[t01], v);
                v = fmaf(wfc, p[t10], v);
                v = fmaf(wcc, p[t11], v);
                acc[ch] = v;
            }
            v0 = acc[0]; v1 = acc[1]; v2 = acc[2];
        } else {
            // exact reference fallback: ind = clip(int32(nx + 224*ny), 0, HW-1)
            int iff = (int)(fx + 224.0f * fy);
            int icf = (int)(cx + 224.0f * fy);
            int ifc = (int)(fx + 224.0f * cy);
            int icc = (int)(cx + 224.0f * cy);
            iff = min(max(iff, 0), HW - 1);
            icf = min(max(icf, 0), HW - 1);
            ifc = min(max(ifc, 0), HW - 1);
            icc = min(max(icc, 0), HW - 1);
            float acc[3];
#pragma unroll
            for (int ch = 0; ch < 3; ch++) {
                const float* p = gim + ch * HW;
                float v = wff * __ldg(p + iff);
                v = fmaf(wcf, __ldg(p + icf), v);
                v = fmaf(wfc, __ldg(p + ifc), v);
                v = fmaf(wcc, __ldg(p + icc), v);
                acc[ch] = v;
            }
            v0 = acc[0]; v1 = acc[1]; v2 = acc[2];
        }
        if (s == 0) { res[0] = v0 * m1v; res[1] = v1 * m1v; res[2] = v2 * m1v; }
        else        { res[0] = fmaf(v0, m2v, res[0]);
                      res[1] = fmaf(v1, m2v, res[1]);
                      res[2] = fmaf(v2, m2v, res[2]); }
    }

    // ── direct coalesced stores (lanes along y) ──
    float* outn = out + n * 3 * HW;
#pragma unroll
    for (int ch = 0; ch < 3; ch++)
        outn[ch * HW + i] = res[ch];
}

extern "C" void kernel_launch(void* const* d_in, const int* in_sizes, int n_in,
                              void* d_out, int out_size)
{
    const float* im1 = (const float*)d_in[0];
    const float* im2 = (const float*)d_in[1];
    const float* C   = (const float*)d_in[2];
    const float* M1  = (const float*)d_in[3];
    const float* M2  = (const float*)d_in[4];
    float* out = (float*)d_out;

    dim3 block(NT, 1, 1);
    dim3 grid(IMG / BXT, IMG / BYT, 64);   // 14 x 7 x 64 = 6272 blocks
    vm_kernel<<<grid, block>>>(im1, im2, C, M1, M2, out);
}

// round 7
// speedup vs baseline: 1.6288x; 1.0298x over previous
#include <cuda_runtime.h>
#include <cstdint>

#define IMG  224
#define HW   (IMG * IMG)        // 50176
#define BXT  16                 // tile x extent (outer dim of flat i, warps)
#define BYT  32                 // tile y extent (inner dim of flat i, lanes)
#define XWU  27                 // staged window width in x
#define SW   29                 // smem row stride in ELEMENTS (odd)
#define YH   43                 // staged window rows in y
#define PLANE (SW * YH)         // 1247 elements per plane
#define NT   512

// compile-time byte offsets inside smem regions
#define PAIR_S (PLANE * 8)      // 9976  : image stride in pair region
#define PAIR_R (16 * SW * 8)    // 3712  : 16-row step in pair region
#define SCAL_S (PLANE * 4)      // 4988
#define SCAL_R (16 * SW * 4)    // 1856

__device__ __forceinline__ uint32_t s2u(const void* p) {
    uint32_t a;
    asm("{ .reg .u64 t; cvta.to.shared.u64 t, %1; cvt.u32.u64 %0, t; }"
        : "=r"(a) : "l"(p));
    return a;
}

// 4B async copy with compile-time dst/src immediate offsets (no per-copy ALU)
template<int DOFF, int SOFF>
__device__ __forceinline__ void cpa(uint32_t db, const float* sb) {
    asm volatile("cp.async.ca.shared.global [%0+%2], [%1+%3], 4;"
                 :: "r"(db), "l"(sb), "n"(DOFF), "n"(SOFF));
}

// stage one (image S, row-step RR) site: ch0,ch1 -> pair plane, ch2 -> scalar
template<int S, int RR>
__device__ __forceinline__ void stage6(uint32_t pb, uint32_t sb_, const float* sp) {
    cpa<S * PAIR_S + RR * PAIR_R + 0, (0 * HW + RR * 16 * IMG) * 4>(pb, sp);
    cpa<S * PAIR_S + RR * PAIR_R + 4, (1 * HW + RR * 16 * IMG) * 4>(pb, sp);
    cpa<S * SCAL_S + RR * SCAL_R,     (2 * HW + RR * 16 * IMG) * 4>(sb_, sp);
}

__global__ __launch_bounds__(NT, 4) void vm_kernel(
    const float* __restrict__ im1, const float* __restrict__ im2,
    const float* __restrict__ C,   const float* __restrict__ M1,
    const float* __restrict__ M2,  float* __restrict__ out)
{
    __shared__ __align__(16) float2 pair[2 * PLANE];  // (ch0,ch1): 19952 B
    __shared__ float              scal[2 * PLANE];    // ch2:       9976 B

    const int tid = threadIdx.x;
    const int l   = tid & 31;             // lane: y within tile
    const int w   = tid >> 5;             // warp: x within tile
    const int X0 = blockIdx.x * BXT;
    const int Y0 = blockIdx.y * BYT;
    const int n  = blockIdx.z;

    // staged window fully inside the image (fallback handles tails exactly)
    const int sx0 = min(max(X0 - 5, 0), IMG - XWU);
    const int sy0 = min(max(Y0 - 5, 0), IMG - YH);

    const float* b1 = im1 + n * 3 * HW;
    const float* b2 = im2 + n * 3 * HW;

    // ── async staging: warp w stages rows {w, w+16, w+32<YH}, lanes 0..26
    //    carry one site each; all offsets beyond two bases are immediates.
    if (l < XWU) {
        const int off0 = (sy0 + w) * IMG + sx0 + l;
        const float* s1p = b1 + off0;
        const float* s2p = b2 + off0;
        const uint32_t pb  = s2u(pair) + (uint32_t)((w * SW + l) * 8);
        const uint32_t sb_ = s2u(scal) + (uint32_t)((w * SW + l) * 4);
        stage6<0, 0>(pb, sb_, s1p);
        stage6<0, 1>(pb, sb_, s1p);
        stage6<1, 0>(pb, sb_, s2p);
        stage6<1, 1>(pb, sb_, s2p);
        if (w < YH - 32) {                // rows 32..42: warps 0..10
            stage6<0, 2>(pb, sb_, s1p);
            stage6<1, 2>(pb, sb_, s2p);
        }
    }
    asm volatile("cp.async.commit_group;");

    // ── coalesced direct I/O (lanes along y) — overlaps staging ──
    const int x = X0 + w;
    const int y = Y0 + l;
    const int i = x * IMG + y;

    float Cx  = __ldg(C  + (n * 2) * HW + i);
    float Cy  = __ldg(C  + (n * 2 + 1) * HW + i);
    float m1v = __ldg(M1 + n * HW + i);
    float m2v = __ldg(M2 + n * HW + i);

    const float fxv = (float)x, fyv = (float)y;
    const float sx0f = (float)sx0, sy0f = (float)sy0;
    const float lox = sx0f, hix = (float)(sx0 + XWU - 1);
    const float loy = sy0f, hiy = (float)(sy0 + YH - 1);

    float pxs[2], pys[2];
    pxs[0] = fxv + Cx; pys[0] = fyv + Cy;
    pxs[1] = fxv - Cx; pys[1] = fyv - Cy;

    asm volatile("cp.async.wait_group 0;");
    __syncthreads();

    float res[3];
#pragma unroll
    for (int s = 0; s < 2; s++) {
        const float px = pxs[s], py = pys[s];

        float fx = floorf(px), cx = ceilf(px);
        float fy = floorf(py), cy = ceilf(py);
        float wfx = 1.0f - (px - fx);
        float wcx = 1.0f - (cx - px);
        float wfy = 1.0f - (py - fy);
        float wcy = 1.0f - (cy - py);
        float wff = wfx * wfy, wcf = wcx * wfy;
        float wfc = wfx * wcy, wcc = wcx * wcy;

        float v0, v1, v2;
        if (fx >= lox && cx <= hix && fy >= loy && cy <= hiy) {
            // window ⊂ image → taps in-image → reference's flat clip is a no-op
            // float-domain exact index math (all values < 2^24)
            float dcf  = cx - fx;                       // 0 or 1
            float drf  = cy - fy;                       // 0 or 1
            float t00f = fmaf(fy - sy0f, (float)SW, fx - sx0f);
            float t10f = fmaf(drf, (float)SW, t00f);
            int t00 = (int)t00f;
            int t01 = (int)(t00f + dcf);
            int t10 = (int)t10f;
            int t11 = (int)(t10f + dcf);

            const float2* pp = pair + s * PLANE;
            const float*  sp = scal + s * PLANE;
            float2 a00 = pp[t00];
            float2 a01 = pp[t01];
            float2 a10 = pp[t10];
            float2 a11 = pp[t11];
            float  c00 = sp[t00];
            float  c01 = sp[t01];
            float  c10 = sp[t10];
            float  c11 = sp[t11];

            v0 = wff * a00.x;
            v0 = fmaf(wcf, a01.x, v0);
            v0 = fmaf(wfc, a10.x, v0);
            v0 = fmaf(wcc, a11.x, v0);
            v1 = wff * a00.y;
            v1 = fmaf(wcf, a01.y, v1);
            v1 = fmaf(wfc, a10.y, v1);
            v1 = fmaf(wcc, a11.y, v1);
            v2 = wff * c00;
            v2 = fmaf(wcf, c01, v2);
            v2 = fmaf(wfc, c10, v2);
            v2 = fmaf(wcc, c11, v2);
        } else {
            // exact reference fallback: ind = clip(int32(nx + 224*ny), 0, HW-1)
            const float* gim = s ? b2 : b1;
            int iff = (int)(fx + 224.0f * fy);
            int icf = (int)(cx + 224.0f * fy);
            int ifc = (int)(fx + 224.0f * cy);
            int icc = (int)(cx + 224.0f * cy);
            iff = min(max(iff, 0), HW - 1);
            icf = min(max(icf, 0), HW - 1);
            ifc = min(max(ifc, 0), HW - 1);
            icc = min(max(icc, 0), HW - 1);
            float acc[3];
#pragma unroll
            for (int ch = 0; ch < 3; ch++) {
                const float* p = gim + ch * HW;
                float v = wff * __ldg(p + iff);
                v = fmaf(wcf, __ldg(p + icf), v);
                v = fmaf(wfc, __ldg(p + ifc), v);
                v = fmaf(wcc, __ldg(p + icc), v);
                acc[ch] = v;
            }
            v0 = acc[0]; v1 = acc[1]; v2 = acc[2];
        }
        if (s == 0) { res[0] = v0 * m1v; res[1] = v1 * m1v; res[2] = v2 * m1v; }
        else        { res[0] = fmaf(v0, m2v, res[0]);
                      res[1] = fmaf(v1, m2v, res[1]);
                      res[2] = fmaf(v2, m2v, res[2]); }
    }

    // ── direct coalesced stores (lanes along y) ──
    float* outn = out + n * 3 * HW;
#pragma unroll
    for (int ch = 0; ch < 3; ch++)
        outn[ch * HW + i] = res[ch];
}

extern "C" void kernel_launch(void* const* d_in, const int* in_sizes, int n_in,
                              void* d_out, int out_size)
{
    const float* im1 = (const float*)d_in[0];
    const float* im2 = (const float*)d_in[1];
    const float* C   = (const float*)d_in[2];
    const float* M1  = (const float*)d_in[3];
    const float* M2  = (const float*)d_in[4];
    float* out = (float*)d_out;

    dim3 block(NT, 1, 1);
    dim3 grid(IMG / BXT, IMG / BYT, 64);   // 14 x 7 x 64 = 6272 blocks
    vm_kernel<<<grid, block>>>(im1, im2, C, M1, M2, out);
}